// round 3
// baseline (speedup 1.0000x reference)
#include <cuda_runtime.h>
#include <cstdint>

#define BB 64
#define NN 8192
#define WW 64
#define HH 4
#define EPSF 1e-8f
#define NCHUNK 32          // 8192 / 256 rows per block

// ---------------- scratch (device globals; no allocation allowed) ----------------
__device__ float g_e[BB * NN * HH];            // exp(score - beta), layout [b][n][h]
__device__ float g_ws[BB * NN * HH];           // unnormalized sharpened weights, [b][n][h]
__device__ float g_parte[BB * HH * NCHUNK];    // partial sums of e   [(b*4+h)*32 + chunk]
__device__ float g_partw[BB * HH * NCHUNK];    // partial sums of ws  [(b*4+h)*32 + chunk]
__device__ float g_parto[NCHUNK * BB * HH * WW]; // partial outputs [chunk][b][h][w]

__device__ __forceinline__ float softplusf(float x) {
    return (x > 20.f) ? x : log1pf(expf(x));
}

// =====================================================================
// Kernel A: content addressing scores -> e = exp(score - beta)
// grid (32, 64), block 256.  Each block: 256 rows of one batch (4 tiles of 64).
// =====================================================================
__global__ void __launch_bounds__(256) k_scores(const float* __restrict__ mem,
                                                const float* __restrict__ ctrl) {
    __shared__ float s_mem[64][68];     // padded: stride 68 floats -> conflict-free LDS.128
    __shared__ float s_keys[4][68];
    __shared__ float s_nk[4];
    __shared__ float s_beta[4];
    __shared__ float s_red[256];

    const int b   = blockIdx.y;
    const int tid = threadIdx.x;
    const float* cb = ctrl + b * 280;

    // keys = tanh(controls[:, :256]); betas = softplus
    {
        int kh = tid >> 6, kw = tid & 63;
        s_keys[kh][kw] = tanhf(cb[kh * 64 + kw]);
    }
    if (tid < 4) s_beta[tid] = softplusf(cb[256 + tid]);
    __syncthreads();
    if (tid < 4) {
        float s = 0.f;
        #pragma unroll
        for (int w = 0; w < 64; w++) { float k = s_keys[tid][w]; s = fmaf(k, k, s); }
        s_nk[tid] = sqrtf(s);
    }
    __syncthreads();

    const int h = tid & 3;
    const int r = tid >> 2;
    const float beta = s_beta[h];
    const float nk   = s_nk[h];
    float sum_local = 0.f;

    const int n0 = blockIdx.x * 256;
    const float* memb = mem + (size_t)b * NN * WW;

    for (int t = 0; t < 4; t++) {
        const int nt = n0 + t * 64;
        __syncthreads();   // previous tile fully consumed
        const float4* src = (const float4*)(memb + (size_t)nt * WW);
        #pragma unroll
        for (int i = 0; i < 4; i++) {
            int idx = tid + i * 256;               // 0..1023
            int rr = idx >> 4, cc = idx & 15;
            *(float4*)&s_mem[rr][cc * 4] = src[idx];
        }
        __syncthreads();

        float dot = 0.f, nm2 = 0.f;
        #pragma unroll
        for (int j = 0; j < 16; j++) {
            float4 m = *(const float4*)&s_mem[r][j * 4];
            float4 k = *(const float4*)&s_keys[h][j * 4];
            dot = fmaf(m.x, k.x, dot); dot = fmaf(m.y, k.y, dot);
            dot = fmaf(m.z, k.z, dot); dot = fmaf(m.w, k.w, dot);
            nm2 = fmaf(m.x, m.x, nm2); nm2 = fmaf(m.y, m.y, nm2);
            nm2 = fmaf(m.z, m.z, nm2); nm2 = fmaf(m.w, m.w, nm2);
        }
        float denom = sqrtf(nm2) * nk + EPSF;
        float score = dot / denom * beta;
        float e = expf(score - beta);            // shift-invariant softmax, score <= beta
        g_e[((size_t)b * NN + nt + r) * 4 + h] = e;   // coalesced: tid = r*4+h
        sum_local += e;
    }

    // block reduction keeping h lanes (stride 4)
    s_red[tid] = sum_local;
    __syncthreads();
    #pragma unroll
    for (int s = 128; s >= 4; s >>= 1) {
        if (tid < s) s_red[tid] += s_red[tid + s];
        __syncthreads();
    }
    if (tid < 4) g_parte[(b * 4 + tid) * NCHUNK + blockIdx.x] = s_red[tid];
}

// =====================================================================
// Kernel B: softmax-normalize, interpolate, circular shift, sharpen
// grid (32, 64), block 256 -> one thread per n, all 4 heads.
// =====================================================================
__global__ void __launch_bounds__(256) k_weights(const float* __restrict__ ctrl,
                                                 const float* __restrict__ prev) {
    __shared__ float s_g[4], s_sh0[4], s_sh1[4], s_sh2[4], s_gam[4], s_inv[4];
    __shared__ float4 s_red[256];

    const int b = blockIdx.y;
    const int tid = threadIdx.x;

    if (tid < 4) {
        const float* cb = ctrl + b * 280;
        s_g[tid]   = 1.f / (1.f + expf(-cb[260 + tid]));
        s_gam[tid] = 1.f + softplusf(cb[276 + tid]);
        float a0 = cb[264 + tid * 3], a1 = cb[265 + tid * 3], a2 = cb[266 + tid * 3];
        float mx = fmaxf(a0, fmaxf(a1, a2));
        float e0 = expf(a0 - mx), e1 = expf(a1 - mx), e2 = expf(a2 - mx);
        float inv3 = 1.f / (e0 + e1 + e2);
        s_sh0[tid] = e0 * inv3; s_sh1[tid] = e1 * inv3; s_sh2[tid] = e2 * inv3;
        const float* pe = g_parte + (b * 4 + tid) * NCHUNK;
        float s = 0.f;
        #pragma unroll
        for (int c = 0; c < NCHUNK; c++) s += pe[c];
        s_inv[tid] = 1.f / s;          // softmax denominator (no EPS per reference)
    }
    __syncthreads();

    const int n  = blockIdx.x * 256 + tid;
    const int nm = (n - 1) & (NN - 1);
    const int np = (n + 1) & (NN - 1);

    const float4* eb = (const float4*)(g_e + (size_t)b * NN * 4);
    float4 em4 = eb[nm], ec4 = eb[n], ep4 = eb[np];
    float emv[4] = {em4.x, em4.y, em4.z, em4.w};
    float ecv[4] = {ec4.x, ec4.y, ec4.z, ec4.w};
    float epv[4] = {ep4.x, ep4.y, ep4.z, ep4.w};

    const float* pb = prev + (size_t)b * HH * NN;

    float wo[4], ls[4];
    #pragma unroll
    for (int h = 0; h < 4; h++) {
        float g = s_g[h], inv = s_inv[h], om = 1.f - g;
        float wim = fmaf(g, emv[h] * inv, om * pb[h * NN + nm]);
        float wic = fmaf(g, ecv[h] * inv, om * pb[h * NN + n]);
        float wip = fmaf(g, epv[h] * inv, om * pb[h * NN + np]);
        float wsf = s_sh0[h] * wim + s_sh1[h] * wic + s_sh2[h] * wip;  // out[i]=s0*w[i-1]+s1*w[i]+s2*w[i+1]
        float wsh = __powf(wsf, s_gam[h]);   // wsf > 0 always
        wo[h] = wsh;
        ls[h] = wsh;
    }
    float4 outv = make_float4(wo[0], wo[1], wo[2], wo[3]);
    *(float4*)(g_ws + ((size_t)b * NN + n) * 4) = outv;

    s_red[tid] = make_float4(ls[0], ls[1], ls[2], ls[3]);
    __syncthreads();
    #pragma unroll
    for (int s = 128; s > 0; s >>= 1) {
        if (tid < s) {
            float4 a = s_red[tid], c = s_red[tid + s];
            s_red[tid] = make_float4(a.x + c.x, a.y + c.y, a.z + c.z, a.w + c.w);
        }
        __syncthreads();
    }
    if (tid < 4) {
        float4 tot = s_red[0];
        float v = (tid == 0) ? tot.x : (tid == 1) ? tot.y : (tid == 2) ? tot.z : tot.w;
        g_partw[(b * 4 + tid) * NCHUNK + blockIdx.x] = v;
    }
}

// =====================================================================
// Kernel C: read = sum_n mem[b][n][w] * ws_norm[b][h][n]  (partial per chunk)
// grid (32, 64), block 256.  thread = (rpar, h, w4), float4 column accumulator.
// =====================================================================
__global__ void __launch_bounds__(256) k_read(const float* __restrict__ mem) {
    __shared__ float  s_mem[64][68];
    __shared__ float4 s_ws[64];
    __shared__ float4 s_acc[4][64];
    __shared__ float  s_inv[4];

    const int b = blockIdx.y;
    const int tid = threadIdx.x;

    if (tid < 4) {
        const float* pw = g_partw + (b * 4 + tid) * NCHUNK;
        float s = 0.f;
        #pragma unroll
        for (int c = 0; c < NCHUNK; c++) s += pw[c];
        s_inv[tid] = 1.f / (s + EPSF);
    }

    const int rpar = tid >> 6;
    const int hw   = tid & 63;
    const int h    = hw >> 4;
    const int w4   = hw & 15;

    const float* memb = mem + (size_t)b * NN * WW;
    const int n0 = blockIdx.x * 256;
    float4 acc = make_float4(0.f, 0.f, 0.f, 0.f);

    for (int t = 0; t < 4; t++) {
        const int nt = n0 + t * 64;
        __syncthreads();
        const float4* src = (const float4*)(memb + (size_t)nt * WW);
        #pragma unroll
        for (int i = 0; i < 4; i++) {
            int idx = tid + i * 256;
            int rr = idx >> 4, cc = idx & 15;
            *(float4*)&s_mem[rr][cc * 4] = src[idx];
        }
        if (tid < 64)
            s_ws[tid] = *(const float4*)(g_ws + ((size_t)b * NN + nt + tid) * 4);
        __syncthreads();

        #pragma unroll
        for (int r0 = 0; r0 < 64; r0 += 4) {
            int r = r0 + rpar;
            float wgt = ((const float*)&s_ws[r])[h];
            float4 m = *(const float4*)&s_mem[r][w4 * 4];
            acc.x = fmaf(wgt, m.x, acc.x);
            acc.y = fmaf(wgt, m.y, acc.y);
            acc.z = fmaf(wgt, m.z, acc.z);
            acc.w = fmaf(wgt, m.w, acc.w);
        }
    }

    __syncthreads();
    s_acc[rpar][hw] = acc;
    __syncthreads();
    if (tid < 64) {
        float4 a = s_acc[0][tid], c1 = s_acc[1][tid], c2 = s_acc[2][tid], c3 = s_acc[3][tid];
        float inv = s_inv[tid >> 4];
        float4 r;
        r.x = (a.x + c1.x + c2.x + c3.x) * inv;
        r.y = (a.y + c1.y + c2.y + c3.y) * inv;
        r.z = (a.z + c1.z + c2.z + c3.z) * inv;
        r.w = (a.w + c1.w + c2.w + c3.w) * inv;
        // hw = tid: h*64 + w4*4 == tid*4
        float* dst = g_parto + (size_t)blockIdx.x * (BB * HH * WW) + b * 256 + tid * 4;
        *(float4*)dst = r;
    }
}

// =====================================================================
// Kernel D: sum 32 chunk partials -> out [B,H,W]
// =====================================================================
__global__ void __launch_bounds__(256) k_final(float* __restrict__ out) {
    const int i = blockIdx.x * 256 + threadIdx.x;   // 0..16383
    float s = 0.f;
    #pragma unroll
    for (int c = 0; c < NCHUNK; c++)
        s += g_parto[(size_t)c * (BB * HH * WW) + i];
    out[i] = s;
}

// =====================================================================
extern "C" void kernel_launch(void* const* d_in, const int* in_sizes, int n_in,
                              void* d_out, int out_size) {
    const float* mem  = nullptr;
    const float* ctrl = nullptr;
    const float* prev = nullptr;
    for (int i = 0; i < n_in; i++) {
        if (in_sizes[i] == BB * NN * WW)      mem  = (const float*)d_in[i];
        else if (in_sizes[i] == BB * 280)     ctrl = (const float*)d_in[i];
        else if (in_sizes[i] == BB * HH * NN) prev = (const float*)d_in[i];
    }

    dim3 grid(NCHUNK, BB);
    k_scores <<<grid, 256>>>(mem, ctrl);
    k_weights<<<grid, 256>>>(ctrl, prev);
    k_read   <<<grid, 256>>>(mem);
    k_final  <<<64,   256>>>((float*)d_out);
}